// round 6
// baseline (speedup 1.0000x reference)
#include <cuda_runtime.h>
#include <cuda_bf16.h>
#include <cstdint>

// Problem constants
#define BATCH 32
#define CIN   256
#define COUT  256
#define Hh    56
#define Ww    56
#define NPIX  (Hh*Ww)          // 3136
#define QDIM  3364             // 58*58 padded pixels per image
#define QPAD  4096             // padded + guard rows per image
#define GOFF  64               // guard offset (rows before q=0)
#define NVALS 100352.0
#define BN_EPS 1e-5

// GEMM config
#define NCHUNK 72              // K = 9 taps * 256 ci ; 72 chunks of k32
#define ROWB   48              // smem row stride (bytes) for 32B k-chunk rows
#define STAGEB (128*ROWB*2)    // A[128][48] + B[128][48] = 12288 B
#define NSTAGE 3

// ----------------- device scratch -----------------
__device__ __align__(256) char  g_xs[(size_t)BATCH * QPAD * CIN];   // 33.5 MB [b][qq][ci] s8
__device__ __align__(256) char  g_ws[9 * COUT * CIN];               // 0.59 MB [tap][co][ci] s8
__device__ float              g_alpha[COUT];
__device__ int                g_sum[COUT];
__device__ unsigned long long g_sumsq[COUT];
__device__ float              g_scale[COUT];
__device__ float              g_shift[COUT];
__device__ __align__(256) short g_S[(size_t)BATCH * NPIX * COUT];   // 51.4 MB [b][p][co]

// ----------------- helpers -----------------
__device__ __forceinline__ uint32_t smem_u32(const void* p) {
    uint32_t a;
    asm("{ .reg .u64 t; cvta.to.shared.u64 t, %1; cvt.u32.u64 %0, t; }" : "=r"(a) : "l"(p));
    return a;
}
__device__ __forceinline__ void cpasync16(uint32_t dst, const void* src) {
    asm volatile("cp.async.cg.shared.global [%0], [%1], 16;" :: "r"(dst), "l"(src) : "memory");
}
__device__ __forceinline__ void mma_s8(int* d, const unsigned* a, const unsigned* b) {
    asm volatile(
        "mma.sync.aligned.m16n8k32.row.col.s32.s8.s8.s32 "
        "{%0,%1,%2,%3}, {%4,%5,%6,%7}, {%8,%9}, {%0,%1,%2,%3};"
        : "+r"(d[0]), "+r"(d[1]), "+r"(d[2]), "+r"(d[3])
        : "r"(a[0]), "r"(a[1]), "r"(a[2]), "r"(a[3]), "r"(b[0]), "r"(b[1]));
}

// ----------------- kernel 1: zero stats -----------------
__global__ void zero_stats_kernel() {
    int t = threadIdx.x;
    if (t < COUT) { g_sum[t] = 0; g_sumsq[t] = 0ull; }
}

// ----------------- kernel 2: zero x buffer -----------------
__global__ void __launch_bounds__(256) zero_xs_kernel() {
    size_t n = (size_t)BATCH * QPAD * CIN / 16;
    uint4* p = (uint4*)g_xs;
    uint4 z = make_uint4(0, 0, 0, 0);
    for (size_t i = (size_t)blockIdx.x * 256 + threadIdx.x; i < n; i += (size_t)gridDim.x * 256) p[i] = z;
}

// ----------------- kernel 3: weight prep (alpha + s8 signs) -----------------
__global__ void __launch_bounds__(256) prep_w_kernel(const float* __restrict__ w) {
    int co = blockIdx.x;
    int ci = threadIdx.x;
    int lane = ci & 31, warp = ci >> 5;

    float v[9];
    const float* wp = w + ((size_t)co * CIN + ci) * 9;
#pragma unroll
    for (int t = 0; t < 9; t++) v[t] = wp[t];

    __shared__ float part[8][9];
    __shared__ float tapmean[9];
#pragma unroll
    for (int t = 0; t < 9; t++) {
        float s = v[t];
#pragma unroll
        for (int o = 16; o > 0; o >>= 1) s += __shfl_down_sync(0xffffffffu, s, o);
        if (lane == 0) part[warp][t] = s;
    }
    __syncthreads();
    if (ci < 9) {
        float s = 0.f;
#pragma unroll
        for (int i = 0; i < 8; i++) s += part[i][ci];
        tapmean[ci] = s * (1.0f / 256.0f);
    }
    __syncthreads();

    float asum = 0.f;
#pragma unroll
    for (int t = 0; t < 9; t++) {
        float wc = v[t] - tapmean[t];
        wc = fminf(fmaxf(wc, -1.0f), 1.0f);
        asum += fabsf(wc);
        int sg = (wc > 0.f) - (wc < 0.f);
        g_ws[((size_t)t * COUT + co) * CIN + ci] = (char)sg;
    }
    __syncthreads();
#pragma unroll
    for (int o = 16; o > 0; o >>= 1) asum += __shfl_down_sync(0xffffffffu, asum, o);
    if (lane == 0) part[warp][0] = asum;
    __syncthreads();
    if (ci == 0) {
        float tot = 0.f;
#pragma unroll
        for (int i = 0; i < 8; i++) tot += part[i][0];
        g_alpha[co] = tot * (1.0f / 2304.0f);
    }
}

// ----------------- kernel 4: binarize x -> g_xs[b][qq][ci] s8 -----------------
__global__ void __launch_bounds__(256) fill_xs_kernel(const float* __restrict__ x) {
    int h = blockIdx.x, b = blockIdx.y;
    int tid = threadIdx.x;
    __shared__ char s[CIN][Ww];

    for (int idx = tid; idx < CIN * Ww; idx += 256) {
        int ci = idx / Ww, w = idx % Ww;
        float v = x[((size_t)(b * CIN + ci)) * NPIX + h * Ww + w];
        s[ci][w] = (char)((v > 0.f) - (v < 0.f));
    }
    __syncthreads();
    // 56 q-rows of 256 bytes, written as char4
    for (int idx = tid; idx < Ww * 64; idx += 256) {
        int w = idx >> 6, c4 = idx & 63;
        char4 pk = make_char4(s[4*c4][w], s[4*c4+1][w], s[4*c4+2][w], s[4*c4+3][w]);
        size_t qq = (size_t)b * QPAD + GOFF + (h + 1) * 58 + (w + 1);
        *(char4*)(g_xs + qq * 256 + 4 * c4) = pk;
    }
}

// ----------------- kernel 5: int8 mma.sync implicit-GEMM conv + fused epilogue -----------------
__global__ void __launch_bounds__(256, 2) conv_mma_kernel() {
    __shared__ __align__(128) char sm[NSTAGE * STAGEB];
    __shared__ int s_sum[128];
    __shared__ int s_sq[128];

    int tid = threadIdx.x, wid = tid >> 5, lane = tid & 31;
    int mwarp = wid & 3;            // 0..3 -> 32 q-rows each
    int nwarp = wid >> 2;           // 0..1 -> 64 couts each
    int n0 = blockIdx.x * 128;
    int q0 = blockIdx.y * 128;
    int b  = blockIdx.z;

    if (tid < 128) { s_sum[tid] = 0; s_sq[tid] = 0; }

    uint32_t sb = smem_u32(sm);
    const char* gx = g_xs + ((size_t)b * QPAD + GOFF) * 256;
    const char* gw = g_ws;

    int crow = tid >> 1, chalf = tid & 1;      // copy assignment: 128 rows x 2 halves

    auto issue_copy = [&](int c) {
        int tap = c >> 3, ci0 = (c & 7) << 5;
        int st = c % NSTAGE;
        int off = (tap / 3 - 1) * 58 + (tap % 3) - 1;
        uint32_t abase = sb + st * STAGEB;
        cpasync16(abase + crow * ROWB + chalf * 16,
                  gx + ((size_t)(q0 + off + crow)) * 256 + ci0 + chalf * 16);
        cpasync16(abase + 128 * ROWB + crow * ROWB + chalf * 16,
                  gw + ((size_t)(tap * COUT + n0 + crow)) * 256 + ci0 + chalf * 16);
        asm volatile("cp.async.commit_group;" ::: "memory");
    };

    int d[2][8][4];
#pragma unroll
    for (int mf = 0; mf < 2; mf++)
#pragma unroll
        for (int nf = 0; nf < 8; nf++)
#pragma unroll
            for (int j = 0; j < 4; j++) d[mf][nf][j] = 0;

    issue_copy(0); issue_copy(1); issue_copy(2);

    for (int k = 0; k < NCHUNK; k++) {
        if (k < NCHUNK - 2)      asm volatile("cp.async.wait_group 2;" ::: "memory");
        else if (k == NCHUNK - 2) asm volatile("cp.async.wait_group 1;" ::: "memory");
        else                      asm volatile("cp.async.wait_group 0;" ::: "memory");
        __syncthreads();

        const char* stg = sm + (k % NSTAGE) * STAGEB;
        // A fragments (warp rows mwarp*32 .. +32, two m16 blocks)
        unsigned a[2][4];
        {
            int r = mwarp * 32 + (lane >> 2);
            int cb = (lane & 3) * 4;
#pragma unroll
            for (int mf = 0; mf < 2; mf++) {
                const char* base = stg + (size_t)(r + mf * 16) * ROWB + cb;
                a[mf][0] = *(const unsigned*)(base);
                a[mf][1] = *(const unsigned*)(base + 8 * ROWB);
                a[mf][2] = *(const unsigned*)(base + 16);
                a[mf][3] = *(const unsigned*)(base + 8 * ROWB + 16);
            }
        }
        // B fragments (warp cols nwarp*64 .. +64, eight n8 blocks)
        unsigned bf[8][2];
        {
            int nrb = nwarp * 64 + (lane >> 2);
            int cb = (lane & 3) * 4;
#pragma unroll
            for (int nf = 0; nf < 8; nf++) {
                const char* base = stg + (size_t)(128 * ROWB) + (size_t)(nrb + nf * 8) * ROWB + cb;
                bf[nf][0] = *(const unsigned*)(base);
                bf[nf][1] = *(const unsigned*)(base + 16);
            }
        }
        __syncthreads();                    // all reads of this stage done
        if (k + NSTAGE < NCHUNK) issue_copy(k + NSTAGE);   // safe to overwrite

#pragma unroll
        for (int mf = 0; mf < 2; mf++)
#pragma unroll
            for (int nf = 0; nf < 8; nf++)
                mma_s8(d[mf][nf], a[mf], bf[nf]);
    }

    // ---- epilogue: S store + channel stats ----
    // output frag: rows lane>>2 (+8), cols (lane&3)*2, +1
    int qb = q0 + mwarp * 32 + (lane >> 2);
    int cpair = (lane & 3) * 2;

    int ls0 = 0, ls1 = 0, lq0 = 0, lq1 = 0;   // per-thread col-pair partials (summed over nf? no — per nf)
#pragma unroll
    for (int nf = 0; nf < 8; nf++) {
        int co = n0 + nwarp * 64 + nf * 8 + cpair;
        int fs0 = 0, fs1 = 0, fq0 = 0, fq1 = 0;
#pragma unroll
        for (int mf = 0; mf < 2; mf++) {
#pragma unroll
            for (int rs = 0; rs < 2; rs++) {
                int q = qb + mf * 16 + rs * 8;
                int r = q / 58, cc = q % 58;
                bool valid = (q < QDIM) && (r >= 1) && (r <= Hh) && (cc >= 1) && (cc <= Ww);
                int v0 = d[mf][nf][rs * 2];
                int v1 = d[mf][nf][rs * 2 + 1];
                if (valid) {
                    int p = (r - 1) * Ww + (cc - 1);
                    unsigned pk = (unsigned)(unsigned short)(short)v0 |
                                  ((unsigned)(unsigned short)(short)v1 << 16);
                    *(unsigned*)(g_S + ((size_t)(b * NPIX) + p) * COUT + co) = pk;
                    fs0 += v0; fs1 += v1;
                    fq0 += v0 * v0; fq1 += v1 * v1;
                }
            }
        }
        // reduce over the 8 lanes sharing this col pair (lane & 3 congruence class)
#pragma unroll
        for (int o = 4; o <= 16; o <<= 1) {
            fs0 += __shfl_xor_sync(0xffffffffu, fs0, o);
            fs1 += __shfl_xor_sync(0xffffffffu, fs1, o);
            fq0 += __shfl_xor_sync(0xffffffffu, fq0, o);
            fq1 += __shfl_xor_sync(0xffffffffu, fq1, o);
        }
        if (lane < 4) {
            int cl = nwarp * 64 + nf * 8 + cpair;
            atomicAdd(&s_sum[cl], fs0);
            atomicAdd(&s_sum[cl + 1], fs1);
            atomicAdd(&s_sq[cl], fq0);
            atomicAdd(&s_sq[cl + 1], fq1);
        }
    }
    (void)ls0; (void)ls1; (void)lq0; (void)lq1;
    __syncthreads();
    if (tid < 128) {
        atomicAdd(&g_sum[n0 + tid], s_sum[tid]);
        atomicAdd(&g_sumsq[n0 + tid], (unsigned long long)(long long)s_sq[tid]);
    }
}

// ----------------- kernel 6: finalize thresholds -----------------
__global__ void finalize_kernel(const float* __restrict__ gamma,
                                const float* __restrict__ beta) {
    int co = threadIdx.x;
    if (co >= COUT) return;
    double s    = (double)g_sum[co];
    double sq   = (double)(long long)g_sumsq[co];
    double mean = s / NVALS;
    double var  = sq / NVALS - mean * mean;
    double a    = (double)g_alpha[co];
    double inv  = 1.0 / sqrt(a * a * var + BN_EPS);
    double sc   = (double)gamma[co] * a * inv;
    g_scale[co] = (float)sc;
    g_shift[co] = (float)((double)beta[co] - sc * mean);
}

// ----------------- kernel 7: threshold + transpose -----------------
__global__ void __launch_bounds__(256) thresh_kernel(float* __restrict__ out) {
    __shared__ float tile[32][33];
    int p0  = blockIdx.x * 32;
    int co0 = blockIdx.y * 32;
    int b   = blockIdx.z;
    int tx  = threadIdx.x, ty = threadIdx.y;

    float sc = g_scale[co0 + tx];
    float sh = g_shift[co0 + tx];
#pragma unroll
    for (int r = 0; r < 4; r++) {
        int pl = ty * 4 + r;
        short s = g_S[((size_t)(b * NPIX + p0 + pl)) * COUT + co0 + tx];
        tile[pl][tx] = (fmaf(sc, (float)s, sh) > 0.0f) ? 1.0f : 0.0f;
    }
    __syncthreads();
#pragma unroll
    for (int r = 0; r < 4; r++) {
        int cl = ty * 4 + r;
        out[((size_t)(b * COUT + co0 + cl)) * NPIX + p0 + tx] = tile[tx][cl];
    }
}

// ----------------- launch -----------------
extern "C" void kernel_launch(void* const* d_in, const int* in_sizes, int n_in,
                              void* d_out, int out_size) {
    const float* x      = (const float*)d_in[0];
    const float* weight = (const float*)d_in[1];
    // bias (d_in[2]) cancels inside training-mode BN
    const float* gamma  = (const float*)d_in[3];
    const float* beta   = (const float*)d_in[4];
    float* out = (float*)d_out;

    zero_stats_kernel<<<1, 256>>>();
    zero_xs_kernel<<<2048, 256>>>();
    prep_w_kernel<<<COUT, 256>>>(weight);
    fill_xs_kernel<<<dim3(Hh, BATCH), 256>>>(x);
    conv_mma_kernel<<<dim3(2, 27, BATCH), 256>>>();   // n-tiles x m-tiles x batch
    finalize_kernel<<<1, 256>>>(gamma, beta);
    thresh_kernel<<<dim3(NPIX / 32, COUT / 32, BATCH), dim3(32, 8)>>>(out);
}